// round 2
// baseline (speedup 1.0000x reference)
#include <cuda_runtime.h>

#define HH 50
#define TT 96
#define NPRED 12
#define NTH 128   // 2 batch elements per block: warps {0,1} and {2,3} -> all 4 SMSPs

// ---- f32x2 packed helpers (FFMA2 path, sm_100+) ----
__device__ __forceinline__ unsigned long long pk2(float lo, float hi) {
    unsigned long long r;
    asm("mov.b64 %0, {%1,%2};" : "=l"(r) : "f"(lo), "f"(hi));
    return r;
}
__device__ __forceinline__ void upk2(unsigned long long v, float &lo, float &hi) {
    asm("mov.b64 {%0,%1}, %2;" : "=f"(lo), "=f"(hi) : "l"(v));
}
__device__ __forceinline__ unsigned long long ffma2(unsigned long long a,
                                                    unsigned long long b,
                                                    unsigned long long c) {
    unsigned long long d;
    asm("fma.rn.f32x2 %0, %1, %2, %3;" : "=l"(d) : "l"(a), "l"(b), "l"(c));
    return d;
}

// sigmoid via EX2 + RCP (MUFU), ~1e-7 rel err
__device__ __forceinline__ float fsig(float x) {
    float e = __expf(-x);
    return __fdividef(1.0f, 1.0f + e);
}
// tanh = 1 - 2u/(1+u), u = exp(-2x); clamp to avoid inf/inf
__device__ __forceinline__ float ftanh(float x) {
    float xc = fminf(fmaxf(x, -15.0f), 15.0f);
    float u = __expf(-2.0f * xc);
    return 1.0f - __fdividef(2.0f * u, 1.0f + u);
}

__global__ __launch_bounds__(NTH)
void lstm_recursive_kernel(const float* __restrict__ x,
                           const float* __restrict__ W_ih,
                           const float* __restrict__ W_hh,
                           const float* __restrict__ b_ih,
                           const float* __restrict__ b_hh,
                           const float* __restrict__ W_fc,
                           const float* __restrict__ b_fc,
                           float* __restrict__ out) {
    const int e = threadIdx.x >> 6;            // element slot within block (0/1)
    const int j = threadIdx.x & 63;            // lane within element
    const int b = blockIdx.x * 2 + e;          // batch element

    __shared__ __align__(16) float sh[2][2][52];   // [elem][double-buffer][h padded]
    __shared__ float swin[2][TT + NPRED];          // sliding input windows
    __shared__ float sred[2][HH];                  // fc reduction scratch

    // load this batch element's input window
    for (int i = j; i < TT; i += 64) swin[e][i] = x[b * TT + i];

    // thread j < 50 owns gate rows j, j+50, j+100, j+150 (i,f,g,o)
    unsigned long long w[4][25];               // 200 regs of packed W_hh pairs
    float wih[4], bsum[4];
    float wfc = 0.0f;
    if (j < HH) {
#pragma unroll
        for (int g = 0; g < 4; g++) {
            const int row = g * HH + j;
            const float2* wr = (const float2*)(W_hh + row * HH);   // 8B aligned
#pragma unroll
            for (int k = 0; k < 25; k++) {
                float2 v = wr[k];
                w[g][k] = pk2(v.x, v.y);
            }
            wih[g]  = W_ih[row];
            bsum[g] = b_ih[row] + b_hh[row];
        }
        wfc = W_fc[j];
    }
    const float bfc = b_fc[0];

    for (int p = 0; p < NPRED; p++) {
        if (j < 52) { sh[e][0][j] = 0.0f; sh[e][1][j] = 0.0f; }
        float c = 0.0f;
        float hnew = 0.0f;
        __syncthreads();

#pragma unroll 1
        for (int t = 0; t < TT; t++) {
            const float xt = swin[e][p + t];
            const float* hbuf = sh[e][t & 1];          // read buffer
            if (j < HH) {
                unsigned long long a0 = pk2(fmaf(xt, wih[0], bsum[0]), 0.0f);
                unsigned long long a1 = pk2(fmaf(xt, wih[1], bsum[1]), 0.0f);
                unsigned long long a2 = pk2(fmaf(xt, wih[2], bsum[2]), 0.0f);
                unsigned long long a3 = pk2(fmaf(xt, wih[3], bsum[3]), 0.0f);

                const ulonglong2* shv = (const ulonglong2*)hbuf;
#pragma unroll
                for (int cc = 0; cc < 12; cc++) {
                    ulonglong2 hv = shv[cc];           // LDS.128: h[4cc..4cc+3]
                    a0 = ffma2(w[0][2 * cc], hv.x, a0);
                    a1 = ffma2(w[1][2 * cc], hv.x, a1);
                    a2 = ffma2(w[2][2 * cc], hv.x, a2);
                    a3 = ffma2(w[3][2 * cc], hv.x, a3);
                    a0 = ffma2(w[0][2 * cc + 1], hv.y, a0);
                    a1 = ffma2(w[1][2 * cc + 1], hv.y, a1);
                    a2 = ffma2(w[2][2 * cc + 1], hv.y, a2);
                    a3 = ffma2(w[3][2 * cc + 1], hv.y, a3);
                }
                {
                    unsigned long long ht = ((const unsigned long long*)hbuf)[24]; // h[48],h[49]
                    a0 = ffma2(w[0][24], ht, a0);
                    a1 = ffma2(w[1][24], ht, a1);
                    a2 = ffma2(w[2][24], ht, a2);
                    a3 = ffma2(w[3][24], ht, a3);
                }
                float l0, h0, l1, h1, l2, h2, l3, h3;
                upk2(a0, l0, h0);
                upk2(a1, l1, h1);
                upk2(a2, l2, h2);
                upk2(a3, l3, h3);
                const float gi = l0 + h0;
                const float gf = l1 + h1;
                const float gg = l2 + h2;
                const float go = l3 + h3;

                const float i_ = fsig(gi);
                const float f_ = fsig(gf);
                const float g_ = ftanh(gg);
                const float o_ = fsig(go);
                c    = fmaf(f_, c, i_ * g_);
                hnew = o_ * ftanh(c);
                sh[e][(t + 1) & 1][j] = hnew;          // write buffer (no race: readers use t&1)
            }
            __syncthreads();                           // new h visible for next step
        }

        // prediction: dot(h, W_fc) + b_fc
        if (j < HH) sred[e][j] = hnew * wfc;
        __syncthreads();
        if (j == 0) {
            float s = bfc;
#pragma unroll
            for (int k = 0; k < HH; k++) s += sred[e][k];
            swin[e][TT + p] = s;                       // slide window
            out[b * NPRED + p] = s;
        }
        __syncthreads();
    }
}

extern "C" void kernel_launch(void* const* d_in, const int* in_sizes, int n_in,
                              void* d_out, int out_size) {
    const float* x    = (const float*)d_in[0];
    const float* W_ih = (const float*)d_in[1];
    const float* W_hh = (const float*)d_in[2];
    const float* b_ih = (const float*)d_in[3];
    const float* b_hh = (const float*)d_in[4];
    const float* W_fc = (const float*)d_in[5];
    const float* b_fc = (const float*)d_in[6];
    float* out = (float*)d_out;

    const int B = out_size / NPRED;               // 1024
    lstm_recursive_kernel<<<B / 2, NTH>>>(x, W_ih, W_hh, b_ih, b_hh, W_fc, b_fc, out);
}

// round 3
// speedup vs baseline: 1.3293x; 1.3293x over previous
#include <cuda_runtime.h>

#define HH 50
#define TT 96
#define NPRED 12
#define NTH 64
#define EPB 2   // batch elements per block (per thread) — weights shared in registers

typedef unsigned long long u64;

// ---- f32x2 packed helpers (FFMA2 path, sm_100+) ----
__device__ __forceinline__ u64 pk2(float lo, float hi) {
    u64 r;
    asm("mov.b64 %0, {%1,%2};" : "=l"(r) : "f"(lo), "f"(hi));
    return r;
}
__device__ __forceinline__ void upk2(u64 v, float &lo, float &hi) {
    asm("mov.b64 {%0,%1}, %2;" : "=f"(lo), "=f"(hi) : "l"(v));
}
__device__ __forceinline__ u64 ffma2(u64 a, u64 b, u64 c) {
    u64 d;
    asm("fma.rn.f32x2 %0, %1, %2, %3;" : "=l"(d) : "l"(a), "l"(b), "l"(c));
    return d;
}

// single-MUFU tanh (sm_75+), then sigmoid via tanh identity
__device__ __forceinline__ float ftanh(float x) {
    float y;
    asm("tanh.approx.f32 %0, %1;" : "=f"(y) : "f"(x));
    return y;
}
__device__ __forceinline__ float fsig(float x) {
    return fmaf(0.5f, ftanh(0.5f * x), 0.5f);
}

__global__ __launch_bounds__(NTH)
void lstm_recursive_kernel(const float* __restrict__ x,
                           const float* __restrict__ W_ih,
                           const float* __restrict__ W_hh,
                           const float* __restrict__ b_ih,
                           const float* __restrict__ b_hh,
                           const float* __restrict__ W_fc,
                           const float* __restrict__ b_fc,
                           float* __restrict__ out) {
    const int j  = threadIdx.x;
    const int b0 = blockIdx.x * EPB;

    __shared__ __align__(16) float sh[EPB][2][52];   // [elem][double-buffer][h padded]
    __shared__ float swin[EPB][TT + NPRED];          // sliding input windows
    __shared__ float sred[EPB][HH];                  // fc reduction scratch

#pragma unroll
    for (int e = 0; e < EPB; e++)
        for (int i = j; i < TT; i += NTH) swin[e][i] = x[(b0 + e) * TT + i];

    // thread j < 50 owns gate rows j, j+50, j+100, j+150 (i,f,g,o) for BOTH elements
    u64 w[4][25];                    // 200 regs of packed W_hh pairs (shared across elements)
    float wih[4], bsum[4];
    float wfc = 0.0f;
    if (j < HH) {
#pragma unroll
        for (int g = 0; g < 4; g++) {
            const int row = g * HH + j;
            const float2* wr = (const float2*)(W_hh + row * HH);   // 8B aligned
#pragma unroll
            for (int k = 0; k < 25; k++) {
                float2 v = wr[k];
                w[g][k] = pk2(v.x, v.y);
            }
            wih[g]  = W_ih[row];
            bsum[g] = b_ih[row] + b_hh[row];
        }
        wfc = W_fc[j];
    }
    const float bfc = b_fc[0];

    for (int p = 0; p < NPRED; p++) {
        if (j < 52) {
#pragma unroll
            for (int e = 0; e < EPB; e++) { sh[e][0][j] = 0.0f; sh[e][1][j] = 0.0f; }
        }
        float c[EPB], hnew[EPB];
#pragma unroll
        for (int e = 0; e < EPB; e++) { c[e] = 0.0f; hnew[e] = 0.0f; }
        __syncthreads();

#pragma unroll 1
        for (int t = 0; t < TT; t++) {
            if (j < HH) {
                u64 a[EPB][4];
#pragma unroll
                for (int e = 0; e < EPB; e++) {
                    const float xt = swin[e][p + t];
                    a[e][0] = pk2(fmaf(xt, wih[0], bsum[0]), 0.0f);
                    a[e][1] = pk2(fmaf(xt, wih[1], bsum[1]), 0.0f);
                    a[e][2] = pk2(fmaf(xt, wih[2], bsum[2]), 0.0f);
                    a[e][3] = pk2(fmaf(xt, wih[3], bsum[3]), 0.0f);
                }
                const ulonglong2* shv0 = (const ulonglong2*)sh[0][t & 1];
                const ulonglong2* shv1 = (const ulonglong2*)sh[1][t & 1];
#pragma unroll
                for (int cc = 0; cc < 12; cc++) {
                    ulonglong2 hvA = shv0[cc];         // LDS.128: hA[4cc..4cc+3]
                    ulonglong2 hvB = shv1[cc];         // LDS.128: hB[4cc..4cc+3]
                    a[0][0] = ffma2(w[0][2 * cc], hvA.x, a[0][0]);
                    a[0][1] = ffma2(w[1][2 * cc], hvA.x, a[0][1]);
                    a[0][2] = ffma2(w[2][2 * cc], hvA.x, a[0][2]);
                    a[0][3] = ffma2(w[3][2 * cc], hvA.x, a[0][3]);
                    a[1][0] = ffma2(w[0][2 * cc], hvB.x, a[1][0]);
                    a[1][1] = ffma2(w[1][2 * cc], hvB.x, a[1][1]);
                    a[1][2] = ffma2(w[2][2 * cc], hvB.x, a[1][2]);
                    a[1][3] = ffma2(w[3][2 * cc], hvB.x, a[1][3]);
                    a[0][0] = ffma2(w[0][2 * cc + 1], hvA.y, a[0][0]);
                    a[0][1] = ffma2(w[1][2 * cc + 1], hvA.y, a[0][1]);
                    a[0][2] = ffma2(w[2][2 * cc + 1], hvA.y, a[0][2]);
                    a[0][3] = ffma2(w[3][2 * cc + 1], hvA.y, a[0][3]);
                    a[1][0] = ffma2(w[0][2 * cc + 1], hvB.y, a[1][0]);
                    a[1][1] = ffma2(w[1][2 * cc + 1], hvB.y, a[1][1]);
                    a[1][2] = ffma2(w[2][2 * cc + 1], hvB.y, a[1][2]);
                    a[1][3] = ffma2(w[3][2 * cc + 1], hvB.y, a[1][3]);
                }
                {
                    u64 htA = ((const u64*)sh[0][t & 1])[24];   // hA[48], hA[49]
                    u64 htB = ((const u64*)sh[1][t & 1])[24];
                    a[0][0] = ffma2(w[0][24], htA, a[0][0]);
                    a[0][1] = ffma2(w[1][24], htA, a[0][1]);
                    a[0][2] = ffma2(w[2][24], htA, a[0][2]);
                    a[0][3] = ffma2(w[3][24], htA, a[0][3]);
                    a[1][0] = ffma2(w[0][24], htB, a[1][0]);
                    a[1][1] = ffma2(w[1][24], htB, a[1][1]);
                    a[1][2] = ffma2(w[2][24], htB, a[1][2]);
                    a[1][3] = ffma2(w[3][24], htB, a[1][3]);
                }
#pragma unroll
                for (int e = 0; e < EPB; e++) {
                    float l0, h0, l1, h1, l2, h2, l3, h3;
                    upk2(a[e][0], l0, h0);
                    upk2(a[e][1], l1, h1);
                    upk2(a[e][2], l2, h2);
                    upk2(a[e][3], l3, h3);
                    const float i_ = fsig(l0 + h0);
                    const float f_ = fsig(l1 + h1);
                    const float g_ = ftanh(l2 + h2);
                    const float o_ = fsig(l3 + h3);
                    c[e]    = fmaf(f_, c[e], i_ * g_);
                    hnew[e] = o_ * ftanh(c[e]);
                    sh[e][(t + 1) & 1][j] = hnew[e];   // write buffer (readers use t&1)
                }
            }
            __syncthreads();                           // new h visible for next step
        }

        // prediction: dot(h, W_fc) + b_fc (one lane per element reduces)
        if (j < HH) {
#pragma unroll
            for (int e = 0; e < EPB; e++) sred[e][j] = hnew[e] * wfc;
        }
        __syncthreads();
        if (j < EPB) {
            float s = bfc;
#pragma unroll
            for (int k = 0; k < HH; k++) s += sred[j][k];
            swin[j][TT + p] = s;                       // slide window
            out[(b0 + j) * NPRED + p] = s;
        }
        __syncthreads();
    }
}

extern "C" void kernel_launch(void* const* d_in, const int* in_sizes, int n_in,
                              void* d_out, int out_size) {
    const float* x    = (const float*)d_in[0];
    const float* W_ih = (const float*)d_in[1];
    const float* W_hh = (const float*)d_in[2];
    const float* b_ih = (const float*)d_in[3];
    const float* b_hh = (const float*)d_in[4];
    const float* W_fc = (const float*)d_in[5];
    const float* b_fc = (const float*)d_in[6];
    float* out = (float*)d_out;

    const int B = out_size / NPRED;               // 1024
    lstm_recursive_kernel<<<B / EPB, NTH>>>(x, W_ih, W_hh, b_ih, b_hh, W_fc, b_fc, out);
}